// round 11
// baseline (speedup 1.0000x reference)
#include <cuda_runtime.h>
#include <cuda_bf16.h>
#include <math.h>

#define N_NODES   65536
#define N_EDGES   1048576
#define IN_DIM    192
#define PE_DIM    64
#define HIDDEN    256
#define LATENT    128
#define NUM_G     64
#define N_PER     1024
#define K_PER     512
#define N_OUT     (NUM_G * K_PER)          // 32768
#define MAX_DEG   128

typedef unsigned long long u64;

// ---------------- packed f32x2 helpers (sm_103a FFMA2 pipe) ------------------
__device__ __forceinline__ u64 ffma2(u64 a, u64 b, u64 c) {
    u64 d;
    asm("fma.rn.f32x2 %0, %1, %2, %3;" : "=l"(d) : "l"(a), "l"(b), "l"(c));
    return d;
}
__device__ __forceinline__ u64 fadd2(u64 a, u64 b) {
    u64 d;
    asm("add.rn.f32x2 %0, %1, %2;" : "=l"(d) : "l"(a), "l"(b));
    return d;
}
__device__ __forceinline__ u64 pack2(float lo, float hi) {
    u64 d;
    asm("mov.b64 %0, {%1, %2};" : "=l"(d) : "f"(lo), "f"(hi));
    return d;
}
__device__ __forceinline__ void unpack2(u64 v, float& lo, float& hi) {
    asm("mov.b64 {%0, %1}, %2;" : "=f"(lo), "=f"(hi) : "l"(v));
}

// ---------------- scratch (device globals; no allocation allowed) -----------
__device__ float g_buf0[N_NODES * 256];
__device__ float g_buf1[N_NODES * 256];
__device__ float g_z[N_NODES * LATENT];
__device__ float g_score[N_NODES];
__device__ float g_dinv[N_NODES];
__device__ int   g_cnt[N_NODES];
__device__ int   g_fill[N_NODES];
__device__ int   g_rowstart[N_NODES + 1];
__device__ int   g_colsrc[N_EDGES];
__device__ int   g_coledge[N_EDGES];
__device__ int   g_perm[N_OUT];
__device__ int   g_is64;

__device__ __forceinline__ int edge_at(const void* __restrict__ ei, int pos) {
    if (g_is64) return (int)((const long long*)ei)[pos];
    return ((const int*)ei)[pos];
}

// ---------------- CSR build ---------------------------------------------------
__global__ void k_zero(const void* __restrict__ ei) {
    int i = blockIdx.x * blockDim.x + threadIdx.x;
    if (i < N_NODES) { g_cnt[i] = 0; g_fill[i] = 0; }
    if (i == 0) {
        const unsigned long long* p = (const unsigned long long*)ei;
        int is64 = 1;
        for (int j = 0; j < 64; j++)
            if (p[j] > 65535ull) { is64 = 0; break; }
        g_is64 = is64;
    }
}

__global__ void k_hist(const void* __restrict__ ei) {
    int e = blockIdx.x * blockDim.x + threadIdx.x;
    if (e < N_EDGES) atomicAdd(&g_cnt[edge_at(ei, N_EDGES + e)], 1);
}

__global__ void k_scan() {
    __shared__ int sh[1024];
    int t = threadIdx.x;
    int base = t * 64;
    int s = 0;
    for (int j = 0; j < 64; j++) s += g_cnt[base + j];
    sh[t] = s;
    __syncthreads();
    int mine = s;
    for (int off = 1; off < 1024; off <<= 1) {
        int v = (t >= off) ? sh[t - off] : 0;
        __syncthreads();
        sh[t] += v;
        __syncthreads();
    }
    int run = sh[t] - mine;
    for (int j = 0; j < 64; j++) {
        int c = g_cnt[base + j];
        g_rowstart[base + j] = run;
        g_dinv[base + j] = (float)(1.0 / sqrt((double)(c + 1)));
        run += c;
    }
    if (t == 1023) g_rowstart[N_NODES] = sh[1023];
}

__global__ void k_scatter(const void* __restrict__ ei) {
    int e = blockIdx.x * blockDim.x + threadIdx.x;
    if (e < N_EDGES) {
        int s = edge_at(ei, e);
        int d = edge_at(ei, N_EDGES + e);
        int pos = g_rowstart[d] + atomicAdd(&g_fill[d], 1);
        g_colsrc[pos] = s;
        g_coledge[pos] = e;
    }
}

__global__ __launch_bounds__(256) void k_sortrows() {
    __shared__ int Es[8][MAX_DEG];
    __shared__ int Ss[8][MAX_DEG];
    int warp = (blockIdx.x * blockDim.x + threadIdx.x) >> 5;
    if (warp >= N_NODES) return;
    int lane = threadIdx.x & 31;
    int w = (threadIdx.x >> 5);
    int e0 = g_rowstart[warp], e1 = g_rowstart[warp + 1];
    int deg = e1 - e0;
    if (deg <= 1) return;
    if (deg > MAX_DEG) deg = MAX_DEG;
    for (int i = lane; i < deg; i += 32) {
        Es[w][i] = g_coledge[e0 + i];
        Ss[w][i] = g_colsrc[e0 + i];
    }
    __syncwarp();
    for (int i = lane; i < deg; i += 32) {
        int my_e = Es[w][i];
        int rank = 0;
        for (int j = 0; j < deg; j++) rank += (Es[w][j] < my_e);
        g_colsrc[e0 + rank] = Ss[w][i];
    }
}

// ---------------- GEMM (f32x2, double-buffered, 128x64 tile — proven 195us) --
template <int MODE>
__global__ __launch_bounds__(256) void k_gemm(
    const float* __restrict__ A0, const float* __restrict__ A1,
    const float* __restrict__ B0, const float* __restrict__ B1,
    float* __restrict__ C)
{
    __shared__ float As[2][16][130];
    __shared__ float Bs[2][16][64];
    int tid = threadIdx.x;
    int tx = tid & 15, ty = tid >> 4;
    int m0 = blockIdx.x * 128;
    int n0 = blockIdx.y * 64;

    int arow0 = tid >> 2;
    int aq0   = (tid & 3) * 4;
    int arow1 = (tid + 256) >> 2;
    int aq1   = aq0;
    int brow  = tid >> 4;
    int bq    = (tid & 15) * 4;

    u64 acc[4][4];
    #pragma unroll
    for (int i = 0; i < 4; i++)
        #pragma unroll
        for (int j = 0; j < 4; j++) acc[i][j] = 0ull;

    float4 va0, va1, vb;
    {
        int col0 = aq0, col1 = aq1;
        if (MODE == 0) {
            va0 = (col0 < IN_DIM) ? *(const float4*)&A0[(m0 + arow0) * IN_DIM + col0]
                                  : *(const float4*)&A1[(m0 + arow0) * PE_DIM + (col0 - IN_DIM)];
            va1 = (col1 < IN_DIM) ? *(const float4*)&A0[(m0 + arow1) * IN_DIM + col1]
                                  : *(const float4*)&A1[(m0 + arow1) * PE_DIM + (col1 - IN_DIM)];
            vb  = *(const float4*)&B0[brow * 256 + n0 + bq];
        } else {
            va0 = *(const float4*)&A0[(m0 + arow0) * 256 + col0];
            va1 = *(const float4*)&A0[(m0 + arow1) * 256 + col1];
            int col = n0 + bq;
            vb = (col < 128) ? *(const float4*)&B0[brow * 128 + col]
                             : *(const float4*)&B1[brow * 128 + (col - 128)];
        }
    }

    #pragma unroll 1
    for (int t = 0; t < 16; t++) {
        int cur = t & 1;
        As[cur][aq0 + 0][arow0] = va0.x; As[cur][aq0 + 1][arow0] = va0.y;
        As[cur][aq0 + 2][arow0] = va0.z; As[cur][aq0 + 3][arow0] = va0.w;
        As[cur][aq1 + 0][arow1] = va1.x; As[cur][aq1 + 1][arow1] = va1.y;
        As[cur][aq1 + 2][arow1] = va1.z; As[cur][aq1 + 3][arow1] = va1.w;
        *(float4*)&Bs[cur][brow][bq] = vb;
        __syncthreads();

        if (t < 15) {
            int k0 = (t + 1) * 16;
            int col0 = k0 + aq0, col1 = k0 + aq1;
            if (MODE == 0) {
                va0 = (col0 < IN_DIM) ? *(const float4*)&A0[(m0 + arow0) * IN_DIM + col0]
                                      : *(const float4*)&A1[(m0 + arow0) * PE_DIM + (col0 - IN_DIM)];
                va1 = (col1 < IN_DIM) ? *(const float4*)&A0[(m0 + arow1) * IN_DIM + col1]
                                      : *(const float4*)&A1[(m0 + arow1) * PE_DIM + (col1 - IN_DIM)];
                vb  = *(const float4*)&B0[(k0 + brow) * 256 + n0 + bq];
            } else {
                va0 = *(const float4*)&A0[(m0 + arow0) * 256 + col0];
                va1 = *(const float4*)&A0[(m0 + arow1) * 256 + col1];
                int col = n0 + bq;
                vb = (col < 128) ? *(const float4*)&B0[(k0 + brow) * 128 + col]
                                 : *(const float4*)&B1[(k0 + brow) * 128 + (col - 128)];
            }
        }

        u64 accT[4][4];
        #pragma unroll
        for (int i = 0; i < 4; i++)
            #pragma unroll
            for (int j = 0; j < 4; j++) accT[i][j] = 0ull;

        #pragma unroll
        for (int k = 0; k < 16; k++) {
            u64 ap[4];
            #pragma unroll
            for (int i = 0; i < 4; i++)
                ap[i] = *(const u64*)&As[cur][k][ty * 8 + 2 * i];
            float4 bv = *(const float4*)&Bs[cur][k][tx * 4];
            u64 bp[4] = { pack2(bv.x, bv.x), pack2(bv.y, bv.y),
                          pack2(bv.z, bv.z), pack2(bv.w, bv.w) };
            #pragma unroll
            for (int i = 0; i < 4; i++)
                #pragma unroll
                for (int j = 0; j < 4; j++)
                    accT[i][j] = ffma2(ap[i], bp[j], accT[i][j]);
        }
        #pragma unroll
        for (int i = 0; i < 4; i++)
            #pragma unroll
            for (int j = 0; j < 4; j++)
                acc[i][j] = fadd2(acc[i][j], accT[i][j]);
        __syncthreads();
    }
    #pragma unroll
    for (int i = 0; i < 4; i++) {
        float lo[4], hi[4];
        #pragma unroll
        for (int j = 0; j < 4; j++) unpack2(acc[i][j], lo[j], hi[j]);
        int r0 = m0 + ty * 8 + 2 * i;
        *(float4*)&C[r0 * 256 + n0 + tx * 4]       = make_float4(lo[0], lo[1], lo[2], lo[3]);
        *(float4*)&C[(r0 + 1) * 256 + n0 + tx * 4] = make_float4(hi[0], hi[1], hi[2], hi[3]);
    }
}

// ---------------- aggregation: 4 warps/node, float2 lanes, 4-edge unroll -----
// Each thread owns features c=w*64+lane*2 (+1). Strict edge-order accumulation
// per feature -> bitwise identical to prior rounds. edges, self loop, bias.
__global__ __launch_bounds__(256) void k_agg4(
    const float* __restrict__ in, float* __restrict__ out,
    const float* __restrict__ bias0, const float* __restrict__ bias1, int relu)
{
    int gw = (blockIdx.x * blockDim.x + threadIdx.x) >> 5;
    if (gw >= N_NODES * 4) return;
    int lane = threadIdx.x & 31;
    int d = gw >> 2;
    int w = gw & 3;
    int off = w * 32 + lane;            // float2 index within 128-float2 row
    const float2* in2 = (const float2*)in;
    float dd = g_dinv[d];

    float a0 = 0.f, a1 = 0.f;
    int e0 = g_rowstart[d], e1 = g_rowstart[d + 1];
    int e = e0;
    for (; e + 3 < e1; e += 4) {
        int s0 = g_colsrc[e],     s1 = g_colsrc[e + 1];
        int s2 = g_colsrc[e + 2], s3 = g_colsrc[e + 3];
        float n0 = __fmul_rn(g_dinv[s0], dd);
        float n1 = __fmul_rn(g_dinv[s1], dd);
        float n2 = __fmul_rn(g_dinv[s2], dd);
        float n3 = __fmul_rn(g_dinv[s3], dd);
        float2 b0 = in2[s0 * 128 + off];
        float2 b1 = in2[s1 * 128 + off];
        float2 b2 = in2[s2 * 128 + off];
        float2 b3 = in2[s3 * 128 + off];
        a0 = __fadd_rn(a0, __fmul_rn(n0, b0.x));
        a1 = __fadd_rn(a1, __fmul_rn(n0, b0.y));
        a0 = __fadd_rn(a0, __fmul_rn(n1, b1.x));
        a1 = __fadd_rn(a1, __fmul_rn(n1, b1.y));
        a0 = __fadd_rn(a0, __fmul_rn(n2, b2.x));
        a1 = __fadd_rn(a1, __fmul_rn(n2, b2.y));
        a0 = __fadd_rn(a0, __fmul_rn(n3, b3.x));
        a1 = __fadd_rn(a1, __fmul_rn(n3, b3.y));
    }
    for (; e < e1; e++) {
        int s0 = g_colsrc[e];
        float n0 = __fmul_rn(g_dinv[s0], dd);
        float2 b0 = in2[s0 * 128 + off];
        a0 = __fadd_rn(a0, __fmul_rn(n0, b0.x));
        a1 = __fadd_rn(a1, __fmul_rn(n0, b0.y));
    }
    {   // self loop last (reference appends loops after edges)
        float ns = __fmul_rn(dd, dd);
        float2 b = in2[d * 128 + off];
        a0 = __fadd_rn(a0, __fmul_rn(ns, b.x));
        a1 = __fadd_rn(a1, __fmul_rn(ns, b.y));
    }
    int c = off * 2;                    // absolute feature index 0..255
    const float* bp = (c < 128) ? bias0 : bias1;
    int cc = c & 127;
    a0 = __fadd_rn(a0, bp[cc]);
    a1 = __fadd_rn(a1, bp[cc + 1]);
    if (relu) { a0 = fmaxf(a0, 0.f); a1 = fmaxf(a1, 0.f); }
    ((float2*)out)[d * 128 + off] = make_float2(a0, a1);
}

// ---------------- z = mu + eps*expf(0.5*lv); score via double dot ------------
__global__ __launch_bounds__(256) void k_zscore(
    const float* __restrict__ eps, const float* __restrict__ w)
{
    int warp = (blockIdx.x * blockDim.x + threadIdx.x) >> 5;
    if (warp >= N_NODES) return;
    int lane = threadIdx.x & 31;
    int n = warp;
    const float4* muv4 = (const float4*)g_buf1;
    float4 mu = muv4[n * 64 + lane];
    float4 lv = muv4[n * 64 + 32 + lane];
    float4 ep = ((const float4*)eps)[n * 32 + lane];
    float4 wv = ((const float4*)w)[lane];
    float4 z;
    z.x = __fadd_rn(mu.x, __fmul_rn(ep.x, expf(__fmul_rn(0.5f, lv.x))));
    z.y = __fadd_rn(mu.y, __fmul_rn(ep.y, expf(__fmul_rn(0.5f, lv.y))));
    z.z = __fadd_rn(mu.z, __fmul_rn(ep.z, expf(__fmul_rn(0.5f, lv.z))));
    z.w = __fadd_rn(mu.w, __fmul_rn(ep.w, expf(__fmul_rn(0.5f, lv.w))));
    double dot = (double)z.x * wv.x + (double)z.y * wv.y
               + (double)z.z * wv.z + (double)z.w * wv.w;
    double wsq = (double)wv.x * wv.x + (double)wv.y * wv.y
               + (double)wv.z * wv.z + (double)wv.w * wv.w;
    #pragma unroll
    for (int o = 16; o > 0; o >>= 1) {
        dot += __shfl_xor_sync(0xffffffffu, dot, o);
        wsq += __shfl_xor_sync(0xffffffffu, wsq, o);
    }
    ((float4*)g_z)[n * 32 + lane] = z;
    if (lane == 0) g_score[n] = (float)tanh(dot / sqrt(wsq));
}

// ---------------- per-graph top-k: bitonic sort of 1024 ----------------------
__device__ __forceinline__ bool later_than(float sa, int ia, float sb, int ib) {
    return (sa < sb) || (sa == sb && ia > ib);
}

__global__ __launch_bounds__(512) void k_topk() {
    __shared__ float ss[1024];
    __shared__ int   si[1024];
    int g = blockIdx.x;
    int t = threadIdx.x;
    int base = g * N_PER;
    ss[t] = g_score[base + t];             si[t] = t;
    ss[t + 512] = g_score[base + t + 512]; si[t + 512] = t + 512;
    __syncthreads();
    for (int k = 2; k <= 1024; k <<= 1) {
        for (int j = k >> 1; j > 0; j >>= 1) {
            for (int i = t; i < 1024; i += 512) {
                int l = i ^ j;
                if (l > i) {
                    bool up = ((i & k) == 0);
                    if (later_than(ss[i], si[i], ss[l], si[l]) == up) {
                        float ts = ss[i]; ss[i] = ss[l]; ss[l] = ts;
                        int ti = si[i]; si[i] = si[l]; si[l] = ti;
                    }
                }
            }
            __syncthreads();
        }
    }
    g_perm[g * K_PER + t] = base + si[t];
}

// ---------------- gather epilogue --------------------------------------------
__global__ __launch_bounds__(256) void k_output(float* __restrict__ out) {
    const int OFF_MU = N_OUT * LATENT;
    const int OFF_LV = 2 * N_OUT * LATENT;
    const int OFF_B  = 3 * N_OUT * LATENT;
    const int OFF_P  = OFF_B + N_OUT;
    int warp = (blockIdx.x * blockDim.x + threadIdx.x) >> 5;
    if (warp >= N_OUT) return;
    int lane = threadIdx.x & 31;
    int node = g_perm[warp];
    float sc = g_score[node];
    float4 z = ((const float4*)g_z)[node * 32 + lane];
    z.x = __fmul_rn(z.x, sc); z.y = __fmul_rn(z.y, sc);
    z.z = __fmul_rn(z.z, sc); z.w = __fmul_rn(z.w, sc);
    ((float4*)out)[warp * 32 + lane] = z;
    const float4* muv4 = (const float4*)g_buf1;
    ((float4*)(out + OFF_MU))[warp * 32 + lane] = muv4[node * 64 + lane];
    ((float4*)(out + OFF_LV))[warp * 32 + lane] = muv4[node * 64 + 32 + lane];
    if (lane == 0) {
        out[OFF_B + warp] = (float)(node >> 10);
        out[OFF_P + warp] = (float)node;
    }
}

// ---------------- launch ------------------------------------------------------
extern "C" void kernel_launch(void* const* d_in, const int* in_sizes, int n_in,
                              void* d_out, int out_size)
{
    const float* x_raw = (const float*)d_in[0];
    const float* pe    = (const float*)d_in[1];
    const void*  ei    = d_in[2];
    const float* eps   = (const float*)d_in[4];
    const float* W1    = (const float*)d_in[5];
    const float* b1    = (const float*)d_in[6];
    const float* Wmu   = (const float*)d_in[7];
    const float* bmu   = (const float*)d_in[8];
    const float* Wlv   = (const float*)d_in[9];
    const float* blv   = (const float*)d_in[10];
    const float* wpool = (const float*)d_in[11];
    float* out = (float*)d_out;

    float* buf0; cudaGetSymbolAddress((void**)&buf0, g_buf0);
    float* buf1; cudaGetSymbolAddress((void**)&buf1, g_buf1);

    static cudaStream_t s2 = 0;
    static cudaEvent_t evFork = 0, evJoin = 0;
    static int init_done = 0;
    if (!init_done) {
        init_done = 1;
        if (cudaStreamCreateWithFlags(&s2, cudaStreamNonBlocking) != cudaSuccess) s2 = 0;
        if (s2) {
            if (cudaEventCreateWithFlags(&evFork, cudaEventDisableTiming) != cudaSuccess ||
                cudaEventCreateWithFlags(&evJoin, cudaEventDisableTiming) != cudaSuccess)
                s2 = 0;
        }
    }

    dim3 gg(N_NODES / 128, 4);
    const int AGG_BLOCKS = (N_NODES * 4 * 32) / 256;   // 4 warps per node

    if (s2) {
        cudaEventRecord(evFork, 0);
        cudaStreamWaitEvent(s2, evFork, 0);
        k_zero<<<N_NODES / 256, 256, 0, s2>>>(ei);
        k_hist<<<N_EDGES / 256, 256, 0, s2>>>(ei);
        k_scan<<<1, 1024, 0, s2>>>();
        k_gemm<0><<<gg, 256>>>(x_raw, pe, W1, nullptr, buf0);   // main stream
        k_scatter<<<N_EDGES / 256, 256, 0, s2>>>(ei);
        k_sortrows<<<(N_NODES * 32) / 256, 256, 0, s2>>>();
        cudaEventRecord(evJoin, s2);
        cudaStreamWaitEvent(0, evJoin, 0);
    } else {
        k_zero<<<N_NODES / 256, 256>>>(ei);
        k_hist<<<N_EDGES / 256, 256>>>(ei);
        k_scan<<<1, 1024>>>();
        k_gemm<0><<<gg, 256>>>(x_raw, pe, W1, nullptr, buf0);
        k_scatter<<<N_EDGES / 256, 256>>>(ei);
        k_sortrows<<<(N_NODES * 32) / 256, 256>>>();
    }

    k_agg4<<<AGG_BLOCKS, 256>>>(buf0, buf1, b1, b1 + 128, 1);
    k_gemm<1><<<gg, 256>>>(buf1, nullptr, Wmu, Wlv, buf0);
    k_agg4<<<AGG_BLOCKS, 256>>>(buf0, buf1, bmu, blv, 0);
    k_zscore<<<(N_NODES * 32) / 256, 256>>>(eps, wpool);
    k_topk<<<NUM_G, 512>>>();
    k_output<<<(N_OUT * 32) / 256, 256>>>(out);
}

// round 12
// speedup vs baseline: 1.0322x; 1.0322x over previous
#include <cuda_runtime.h>
#include <cuda_bf16.h>
#include <math.h>

#define N_NODES   65536
#define N_EDGES   1048576
#define IN_DIM    192
#define PE_DIM    64
#define HIDDEN    256
#define LATENT    128
#define NUM_G     64
#define N_PER     1024
#define K_PER     512
#define N_OUT     (NUM_G * K_PER)          // 32768
#define MAX_DEG   128

typedef unsigned long long u64;

// ---------------- packed f32x2 helpers (sm_103a FFMA2 pipe) ------------------
__device__ __forceinline__ u64 ffma2(u64 a, u64 b, u64 c) {
    u64 d;
    asm("fma.rn.f32x2 %0, %1, %2, %3;" : "=l"(d) : "l"(a), "l"(b), "l"(c));
    return d;
}
__device__ __forceinline__ u64 fadd2(u64 a, u64 b) {
    u64 d;
    asm("add.rn.f32x2 %0, %1, %2;" : "=l"(d) : "l"(a), "l"(b));
    return d;
}
__device__ __forceinline__ u64 pack2(float lo, float hi) {
    u64 d;
    asm("mov.b64 %0, {%1, %2};" : "=l"(d) : "f"(lo), "f"(hi));
    return d;
}
__device__ __forceinline__ void unpack2(u64 v, float& lo, float& hi) {
    asm("mov.b64 {%0, %1}, %2;" : "=f"(lo), "=f"(hi) : "l"(v));
}

// ---------------- scratch (device globals; no allocation allowed) -----------
__device__ float g_buf0[N_NODES * 256];
__device__ float g_buf1[N_NODES * 256];
__device__ float g_z[N_NODES * LATENT];
__device__ float g_score[N_NODES];
__device__ float g_dinv[N_NODES];
__device__ int   g_cnt[N_NODES];
__device__ int   g_fill[N_NODES];
__device__ int   g_rowstart[N_NODES + 1];
__device__ int   g_colsrc[N_EDGES];
__device__ int   g_coledge[N_EDGES];
__device__ int2  g_edge[N_EDGES];          // (src, weight bits) per CSR slot
__device__ int   g_perm[N_OUT];
__device__ int   g_is64;

__device__ __forceinline__ int edge_at(const void* __restrict__ ei, int pos) {
    if (g_is64) return (int)((const long long*)ei)[pos];
    return ((const int*)ei)[pos];
}

// ---------------- CSR build ---------------------------------------------------
__global__ void k_zero(const void* __restrict__ ei) {
    int i = blockIdx.x * blockDim.x + threadIdx.x;
    if (i < N_NODES) { g_cnt[i] = 0; g_fill[i] = 0; }
    if (i == 0) {
        const unsigned long long* p = (const unsigned long long*)ei;
        int is64 = 1;
        for (int j = 0; j < 64; j++)
            if (p[j] > 65535ull) { is64 = 0; break; }
        g_is64 = is64;
    }
}

__global__ void k_hist(const void* __restrict__ ei) {
    int e = blockIdx.x * blockDim.x + threadIdx.x;
    if (e < N_EDGES) atomicAdd(&g_cnt[edge_at(ei, N_EDGES + e)], 1);
}

__global__ void k_scan() {
    __shared__ int sh[1024];
    int t = threadIdx.x;
    int base = t * 64;
    int s = 0;
    for (int j = 0; j < 64; j++) s += g_cnt[base + j];
    sh[t] = s;
    __syncthreads();
    int mine = s;
    for (int off = 1; off < 1024; off <<= 1) {
        int v = (t >= off) ? sh[t - off] : 0;
        __syncthreads();
        sh[t] += v;
        __syncthreads();
    }
    int run = sh[t] - mine;
    for (int j = 0; j < 64; j++) {
        int c = g_cnt[base + j];
        g_rowstart[base + j] = run;
        g_dinv[base + j] = (float)(1.0 / sqrt((double)(c + 1)));
        run += c;
    }
    if (t == 1023) g_rowstart[N_NODES] = sh[1023];
}

__global__ void k_scatter(const void* __restrict__ ei) {
    int e = blockIdx.x * blockDim.x + threadIdx.x;
    if (e < N_EDGES) {
        int s = edge_at(ei, e);
        int d = edge_at(ei, N_EDGES + e);
        int pos = g_rowstart[d] + atomicAdd(&g_fill[d], 1);
        g_colsrc[pos] = s;
        g_coledge[pos] = e;
    }
}

// sort each CSR row by edge id AND pack (src, weight) records
__global__ __launch_bounds__(256) void k_sortrows() {
    __shared__ int Es[8][MAX_DEG];
    __shared__ int Ss[8][MAX_DEG];
    int warp = (blockIdx.x * blockDim.x + threadIdx.x) >> 5;
    if (warp >= N_NODES) return;
    int lane = threadIdx.x & 31;
    int w = (threadIdx.x >> 5);
    int e0 = g_rowstart[warp], e1 = g_rowstart[warp + 1];
    int deg = e1 - e0;
    if (deg <= 0) return;
    float dd = g_dinv[warp];
    if (deg == 1) {
        if (lane == 0) {
            int s = g_colsrc[e0];
            g_edge[e0] = make_int2(s, __float_as_int(__fmul_rn(g_dinv[s], dd)));
        }
        return;
    }
    if (deg > MAX_DEG) deg = MAX_DEG;
    for (int i = lane; i < deg; i += 32) {
        Es[w][i] = g_coledge[e0 + i];
        Ss[w][i] = g_colsrc[e0 + i];
    }
    __syncwarp();
    for (int i = lane; i < deg; i += 32) {
        int my_e = Es[w][i];
        int rank = 0;
        for (int j = 0; j < deg; j++) rank += (Es[w][j] < my_e);
        int s = Ss[w][i];
        g_edge[e0 + rank] = make_int2(s, __float_as_int(__fmul_rn(g_dinv[s], dd)));
    }
}

// ---------------- GEMM (f32x2, double-buffered, 128x64 tile — proven 195us) --
template <int MODE>
__global__ __launch_bounds__(256) void k_gemm(
    const float* __restrict__ A0, const float* __restrict__ A1,
    const float* __restrict__ B0, const float* __restrict__ B1,
    float* __restrict__ C)
{
    __shared__ float As[2][16][130];
    __shared__ float Bs[2][16][64];
    int tid = threadIdx.x;
    int tx = tid & 15, ty = tid >> 4;
    int m0 = blockIdx.x * 128;
    int n0 = blockIdx.y * 64;

    int arow0 = tid >> 2;
    int aq0   = (tid & 3) * 4;
    int arow1 = (tid + 256) >> 2;
    int aq1   = aq0;
    int brow  = tid >> 4;
    int bq    = (tid & 15) * 4;

    u64 acc[4][4];
    #pragma unroll
    for (int i = 0; i < 4; i++)
        #pragma unroll
        for (int j = 0; j < 4; j++) acc[i][j] = 0ull;

    float4 va0, va1, vb;
    {
        int col0 = aq0, col1 = aq1;
        if (MODE == 0) {
            va0 = (col0 < IN_DIM) ? *(const float4*)&A0[(m0 + arow0) * IN_DIM + col0]
                                  : *(const float4*)&A1[(m0 + arow0) * PE_DIM + (col0 - IN_DIM)];
            va1 = (col1 < IN_DIM) ? *(const float4*)&A0[(m0 + arow1) * IN_DIM + col1]
                                  : *(const float4*)&A1[(m0 + arow1) * PE_DIM + (col1 - IN_DIM)];
            vb  = *(const float4*)&B0[brow * 256 + n0 + bq];
        } else {
            va0 = *(const float4*)&A0[(m0 + arow0) * 256 + col0];
            va1 = *(const float4*)&A0[(m0 + arow1) * 256 + col1];
            int col = n0 + bq;
            vb = (col < 128) ? *(const float4*)&B0[brow * 128 + col]
                             : *(const float4*)&B1[brow * 128 + (col - 128)];
        }
    }

    #pragma unroll 1
    for (int t = 0; t < 16; t++) {
        int cur = t & 1;
        As[cur][aq0 + 0][arow0] = va0.x; As[cur][aq0 + 1][arow0] = va0.y;
        As[cur][aq0 + 2][arow0] = va0.z; As[cur][aq0 + 3][arow0] = va0.w;
        As[cur][aq1 + 0][arow1] = va1.x; As[cur][aq1 + 1][arow1] = va1.y;
        As[cur][aq1 + 2][arow1] = va1.z; As[cur][aq1 + 3][arow1] = va1.w;
        *(float4*)&Bs[cur][brow][bq] = vb;
        __syncthreads();

        if (t < 15) {
            int k0 = (t + 1) * 16;
            int col0 = k0 + aq0, col1 = k0 + aq1;
            if (MODE == 0) {
                va0 = (col0 < IN_DIM) ? *(const float4*)&A0[(m0 + arow0) * IN_DIM + col0]
                                      : *(const float4*)&A1[(m0 + arow0) * PE_DIM + (col0 - IN_DIM)];
                va1 = (col1 < IN_DIM) ? *(const float4*)&A0[(m0 + arow1) * IN_DIM + col1]
                                      : *(const float4*)&A1[(m0 + arow1) * PE_DIM + (col1 - IN_DIM)];
                vb  = *(const float4*)&B0[(k0 + brow) * 256 + n0 + bq];
            } else {
                va0 = *(const float4*)&A0[(m0 + arow0) * 256 + col0];
                va1 = *(const float4*)&A0[(m0 + arow1) * 256 + col1];
                int col = n0 + bq;
                vb = (col < 128) ? *(const float4*)&B0[(k0 + brow) * 128 + col]
                                 : *(const float4*)&B1[(k0 + brow) * 128 + (col - 128)];
            }
        }

        u64 accT[4][4];
        #pragma unroll
        for (int i = 0; i < 4; i++)
            #pragma unroll
            for (int j = 0; j < 4; j++) accT[i][j] = 0ull;

        #pragma unroll
        for (int k = 0; k < 16; k++) {
            u64 ap[4];
            #pragma unroll
            for (int i = 0; i < 4; i++)
                ap[i] = *(const u64*)&As[cur][k][ty * 8 + 2 * i];
            float4 bv = *(const float4*)&Bs[cur][k][tx * 4];
            u64 bp[4] = { pack2(bv.x, bv.x), pack2(bv.y, bv.y),
                          pack2(bv.z, bv.z), pack2(bv.w, bv.w) };
            #pragma unroll
            for (int i = 0; i < 4; i++)
                #pragma unroll
                for (int j = 0; j < 4; j++)
                    accT[i][j] = ffma2(ap[i], bp[j], accT[i][j]);
        }
        #pragma unroll
        for (int i = 0; i < 4; i++)
            #pragma unroll
            for (int j = 0; j < 4; j++)
                acc[i][j] = fadd2(acc[i][j], accT[i][j]);
        __syncthreads();
    }
    #pragma unroll
    for (int i = 0; i < 4; i++) {
        float lo[4], hi[4];
        #pragma unroll
        for (int j = 0; j < 4; j++) unpack2(acc[i][j], lo[j], hi[j]);
        int r0 = m0 + ty * 8 + 2 * i;
        *(float4*)&C[r0 * 256 + n0 + tx * 4]       = make_float4(lo[0], lo[1], lo[2], lo[3]);
        *(float4*)&C[(r0 + 1) * 256 + n0 + tx * 4] = make_float4(hi[0], hi[1], hi[2], hi[3]);
    }
}

// ----- aggregation: 2 warps/node, float4 lanes, pipelined packed edges -------
// acc += w_e * in[src] in strict edge order; self loop; bias; optional relu.
__global__ __launch_bounds__(256) void k_agg(
    const float* __restrict__ in, float* __restrict__ out,
    const float* __restrict__ bias0, const float* __restrict__ bias1, int relu)
{
    int gw = (blockIdx.x * blockDim.x + threadIdx.x) >> 5;
    if (gw >= N_NODES * 2) return;
    int lane = threadIdx.x & 31;
    int d = gw >> 1;
    int half = gw & 1;
    const float4* in4 = (const float4*)in + half * 32;
    float dd = g_dinv[d];

    float a0 = 0.f, a1 = 0.f, a2 = 0.f, a3 = 0.f;
    int e0 = g_rowstart[d], e1 = g_rowstart[d + 1];
    int e = e0;

    if (e + 3 < e1) {
        int2 er[4];
        #pragma unroll
        for (int u = 0; u < 4; u++) er[u] = g_edge[e + u];
        // pipelined: prefetch batch t+1 while gathering/accumulating batch t
        for (; e + 7 < e1; e += 4) {
            int2 ern[4];
            #pragma unroll
            for (int u = 0; u < 4; u++) ern[u] = g_edge[e + 4 + u];
            float4 b[4];
            #pragma unroll
            for (int u = 0; u < 4; u++) b[u] = in4[er[u].x * 64 + lane];
            #pragma unroll
            for (int u = 0; u < 4; u++) {
                float n = __int_as_float(er[u].y);
                a0 = __fadd_rn(a0, __fmul_rn(n, b[u].x));
                a1 = __fadd_rn(a1, __fmul_rn(n, b[u].y));
                a2 = __fadd_rn(a2, __fmul_rn(n, b[u].z));
                a3 = __fadd_rn(a3, __fmul_rn(n, b[u].w));
            }
            #pragma unroll
            for (int u = 0; u < 4; u++) er[u] = ern[u];
        }
        {   // drain the in-flight batch
            float4 b[4];
            #pragma unroll
            for (int u = 0; u < 4; u++) b[u] = in4[er[u].x * 64 + lane];
            #pragma unroll
            for (int u = 0; u < 4; u++) {
                float n = __int_as_float(er[u].y);
                a0 = __fadd_rn(a0, __fmul_rn(n, b[u].x));
                a1 = __fadd_rn(a1, __fmul_rn(n, b[u].y));
                a2 = __fadd_rn(a2, __fmul_rn(n, b[u].z));
                a3 = __fadd_rn(a3, __fmul_rn(n, b[u].w));
            }
            e += 4;
        }
    }
    for (; e < e1; e++) {
        int2 ee = g_edge[e];
        float n0 = __int_as_float(ee.y);
        float4 b0 = in4[ee.x * 64 + lane];
        a0 = __fadd_rn(a0, __fmul_rn(n0, b0.x));
        a1 = __fadd_rn(a1, __fmul_rn(n0, b0.y));
        a2 = __fadd_rn(a2, __fmul_rn(n0, b0.z));
        a3 = __fadd_rn(a3, __fmul_rn(n0, b0.w));
    }
    {   // self loop last (reference appends loops after edges)
        float ns = __fmul_rn(dd, dd);
        float4 b = in4[d * 64 + lane];
        a0 = __fadd_rn(a0, __fmul_rn(ns, b.x));
        a1 = __fadd_rn(a1, __fmul_rn(ns, b.y));
        a2 = __fadd_rn(a2, __fmul_rn(ns, b.z));
        a3 = __fadd_rn(a3, __fmul_rn(ns, b.w));
    }
    const float* bias = half ? bias1 : bias0;
    int c = lane * 4;
    a0 = __fadd_rn(a0, bias[c + 0]);
    a1 = __fadd_rn(a1, bias[c + 1]);
    a2 = __fadd_rn(a2, bias[c + 2]);
    a3 = __fadd_rn(a3, bias[c + 3]);
    if (relu) {
        a0 = fmaxf(a0, 0.f); a1 = fmaxf(a1, 0.f);
        a2 = fmaxf(a2, 0.f); a3 = fmaxf(a3, 0.f);
    }
    ((float4*)out + half * 32)[d * 64 + lane] = make_float4(a0, a1, a2, a3);
}

// ---------------- z = mu + eps*expf(0.5*lv); score via double dot ------------
__global__ __launch_bounds__(256) void k_zscore(
    const float* __restrict__ eps, const float* __restrict__ w)
{
    int warp = (blockIdx.x * blockDim.x + threadIdx.x) >> 5;
    if (warp >= N_NODES) return;
    int lane = threadIdx.x & 31;
    int n = warp;
    const float4* muv4 = (const float4*)g_buf1;
    float4 mu = muv4[n * 64 + lane];
    float4 lv = muv4[n * 64 + 32 + lane];
    float4 ep = ((const float4*)eps)[n * 32 + lane];
    float4 wv = ((const float4*)w)[lane];
    float4 z;
    z.x = __fadd_rn(mu.x, __fmul_rn(ep.x, expf(__fmul_rn(0.5f, lv.x))));
    z.y = __fadd_rn(mu.y, __fmul_rn(ep.y, expf(__fmul_rn(0.5f, lv.y))));
    z.z = __fadd_rn(mu.z, __fmul_rn(ep.z, expf(__fmul_rn(0.5f, lv.z))));
    z.w = __fadd_rn(mu.w, __fmul_rn(ep.w, expf(__fmul_rn(0.5f, lv.w))));
    double dot = (double)z.x * wv.x + (double)z.y * wv.y
               + (double)z.z * wv.z + (double)z.w * wv.w;
    double wsq = (double)wv.x * wv.x + (double)wv.y * wv.y
               + (double)wv.z * wv.z + (double)wv.w * wv.w;
    #pragma unroll
    for (int o = 16; o > 0; o >>= 1) {
        dot += __shfl_xor_sync(0xffffffffu, dot, o);
        wsq += __shfl_xor_sync(0xffffffffu, wsq, o);
    }
    ((float4*)g_z)[n * 32 + lane] = z;
    if (lane == 0) g_score[n] = (float)tanh(dot / sqrt(wsq));
}

// ---------------- per-graph top-k: bitonic sort of 1024 ----------------------
__device__ __forceinline__ bool later_than(float sa, int ia, float sb, int ib) {
    return (sa < sb) || (sa == sb && ia > ib);
}

__global__ __launch_bounds__(512) void k_topk() {
    __shared__ float ss[1024];
    __shared__ int   si[1024];
    int g = blockIdx.x;
    int t = threadIdx.x;
    int base = g * N_PER;
    ss[t] = g_score[base + t];             si[t] = t;
    ss[t + 512] = g_score[base + t + 512]; si[t + 512] = t + 512;
    __syncthreads();
    for (int k = 2; k <= 1024; k <<= 1) {
        for (int j = k >> 1; j > 0; j >>= 1) {
            for (int i = t; i < 1024; i += 512) {
                int l = i ^ j;
                if (l > i) {
                    bool up = ((i & k) == 0);
                    if (later_than(ss[i], si[i], ss[l], si[l]) == up) {
                        float ts = ss[i]; ss[i] = ss[l]; ss[l] = ts;
                        int ti = si[i]; si[i] = si[l]; si[l] = ti;
                    }
                }
            }
            __syncthreads();
        }
    }
    g_perm[g * K_PER + t] = base + si[t];
}

// ---------------- gather epilogue --------------------------------------------
__global__ __launch_bounds__(256) void k_output(float* __restrict__ out) {
    const int OFF_MU = N_OUT * LATENT;
    const int OFF_LV = 2 * N_OUT * LATENT;
    const int OFF_B  = 3 * N_OUT * LATENT;
    const int OFF_P  = OFF_B + N_OUT;
    int warp = (blockIdx.x * blockDim.x + threadIdx.x) >> 5;
    if (warp >= N_OUT) return;
    int lane = threadIdx.x & 31;
    int node = g_perm[warp];
    float sc = g_score[node];
    float4 z = ((const float4*)g_z)[node * 32 + lane];
    z.x = __fmul_rn(z.x, sc); z.y = __fmul_rn(z.y, sc);
    z.z = __fmul_rn(z.z, sc); z.w = __fmul_rn(z.w, sc);
    ((float4*)out)[warp * 32 + lane] = z;
    const float4* muv4 = (const float4*)g_buf1;
    ((float4*)(out + OFF_MU))[warp * 32 + lane] = muv4[node * 64 + lane];
    ((float4*)(out + OFF_LV))[warp * 32 + lane] = muv4[node * 64 + 32 + lane];
    if (lane == 0) {
        out[OFF_B + warp] = (float)(node >> 10);
        out[OFF_P + warp] = (float)node;
    }
}

// ---------------- launch ------------------------------------------------------
extern "C" void kernel_launch(void* const* d_in, const int* in_sizes, int n_in,
                              void* d_out, int out_size)
{
    const float* x_raw = (const float*)d_in[0];
    const float* pe    = (const float*)d_in[1];
    const void*  ei    = d_in[2];
    const float* eps   = (const float*)d_in[4];
    const float* W1    = (const float*)d_in[5];
    const float* b1    = (const float*)d_in[6];
    const float* Wmu   = (const float*)d_in[7];
    const float* bmu   = (const float*)d_in[8];
    const float* Wlv   = (const float*)d_in[9];
    const float* blv   = (const float*)d_in[10];
    const float* wpool = (const float*)d_in[11];
    float* out = (float*)d_out;

    float* buf0; cudaGetSymbolAddress((void**)&buf0, g_buf0);
    float* buf1; cudaGetSymbolAddress((void**)&buf1, g_buf1);

    static cudaStream_t s2 = 0;
    static cudaEvent_t evFork = 0, evJoin = 0;
    static int init_done = 0;
    if (!init_done) {
        init_done = 1;
        if (cudaStreamCreateWithFlags(&s2, cudaStreamNonBlocking) != cudaSuccess) s2 = 0;
        if (s2) {
            if (cudaEventCreateWithFlags(&evFork, cudaEventDisableTiming) != cudaSuccess ||
                cudaEventCreateWithFlags(&evJoin, cudaEventDisableTiming) != cudaSuccess)
                s2 = 0;
        }
    }

    dim3 gg(N_NODES / 128, 4);

    if (s2) {
        cudaEventRecord(evFork, 0);
        cudaStreamWaitEvent(s2, evFork, 0);
        k_zero<<<N_NODES / 256, 256, 0, s2>>>(ei);
        k_hist<<<N_EDGES / 256, 256, 0, s2>>>(ei);
        k_scan<<<1, 1024, 0, s2>>>();
        k_gemm<0><<<gg, 256>>>(x_raw, pe, W1, nullptr, buf0);   // main stream
        k_scatter<<<N_EDGES / 256, 256, 0, s2>>>(ei);
        k_sortrows<<<(N_NODES * 32) / 256, 256, 0, s2>>>();
        cudaEventRecord(evJoin, s2);
        cudaStreamWaitEvent(0, evJoin, 0);
    } else {
        k_zero<<<N_NODES / 256, 256>>>(ei);
        k_hist<<<N_EDGES / 256, 256>>>(ei);
        k_scan<<<1, 1024>>>();
        k_gemm<0><<<gg, 256>>>(x_raw, pe, W1, nullptr, buf0);
        k_scatter<<<N_EDGES / 256, 256>>>(ei);
        k_sortrows<<<(N_NODES * 32) / 256, 256>>>();
    }

    k_agg<<<(N_NODES * 64) / 256, 256>>>(buf0, buf1, b1, b1 + 128, 1);
    k_gemm<1><<<gg, 256>>>(buf1, nullptr, Wmu, Wlv, buf0);
    k_agg<<<(N_NODES * 64) / 256, 256>>>(buf0, buf1, bmu, blv, 0);
    k_zscore<<<(N_NODES * 32) / 256, 256>>>(eps, wpool);
    k_topk<<<NUM_G, 512>>>();
    k_output<<<(N_OUT * 32) / 256, 256>>>(out);
}